// round 3
// baseline (speedup 1.0000x reference)
#include <cuda_runtime.h>
#include <math.h>

#define Sn 512
#define Bn 128
#define En 300
#define Hn 256
#define G4 1024
#define Cn 6
#define Pn 256
#define H2 512
#define G3 1536
#define GC 64   // CTAs per LSTM direction

// ---------------- scratch (static device allocations; no cudaMalloc) --------
__device__ float g_emb[Sn * Bn * En];          // [S][B][E] time-major, tanh'ed
__device__ float g_gxf[Sn * Bn * G4];          // fwd input gates (+bih+bhh)
__device__ float g_gxb[Sn * Bn * G4];          // bwd input gates (unpermuted)
__device__ float g_hbuf[2 * 2 * Bn * Hn];      // [phase][dir][b][h]
__device__ float g_hdec[2][Bn * H2];           // decoder hidden double buffer
__device__ float g_gxd[Cn * G3];               // decoder input gates (+d_bih)
__device__ float g_dT[H2 * G3];                // d_Whh transposed [k][j]
__device__ float g_pT[H2 * Pn];                // proj_W transposed [k][j]
__device__ unsigned g_bar[2];                  // per-direction barrier counters

// ---------------- reset (per replay: barrier counters + initial h/c state) --
__global__ void reset_kernel() {
    int i = blockIdx.x * blockDim.x + threadIdx.x;
    if (i < 2) g_bar[i] = 0u;
    for (int j = i; j < 2 * 2 * Bn * Hn; j += gridDim.x * blockDim.x)
        g_hbuf[j] = 0.f;
}

// ---------------- embedding: g_emb[s][b][:] = tanh(embed_W[seq[b][s]]) ------
__global__ void embed_kernel(const int* __restrict__ seq,
                             const float* __restrict__ embW) {
    int m = blockIdx.x;          // m = s*128 + b
    int s = m >> 7, b = m & 127;
    int tok = seq[b * Sn + s];
    const float* src = embW + (size_t)tok * En;
    float* dst = g_emb + (size_t)m * En;
    for (int e = threadIdx.x; e < En; e += blockDim.x)
        dst[e] = tanhf(src[e]);
}

// ---------------- SGEMM: C[M,N] = A[M,K] * W[N,K]^T + b1[n] + b2[n] ---------
// BM=BN=128, BK=8, 256 threads, 8x8 per thread.
__global__ void __launch_bounds__(256, 2)
sgemm_nt(const float* __restrict__ A, const float* __restrict__ W,
         const float* __restrict__ b1, const float* __restrict__ b2,
         float* __restrict__ C, int M, int N, int K) {
    __shared__ float As[8][128];
    __shared__ float Ws[8][128];
    int bm = blockIdx.y * 128, bn = blockIdx.x * 128;
    int t = threadIdx.x;
    int tx = t & 15, ty = t >> 4;
    int lr = t >> 1;           // 0..127
    int lc = (t & 1) * 4;      // 0 or 4
    float acc[8][8];
#pragma unroll
    for (int i = 0; i < 8; i++)
#pragma unroll
        for (int j = 0; j < 8; j++) acc[i][j] = 0.f;

    for (int k0 = 0; k0 < K; k0 += 8) {
#pragma unroll
        for (int i = 0; i < 4; i++) {
            int k = k0 + lc + i;
            As[lc + i][lr] = (k < K) ? A[(size_t)(bm + lr) * K + k] : 0.f;
            Ws[lc + i][lr] = (k < K) ? W[(size_t)(bn + lr) * K + k] : 0.f;
        }
        __syncthreads();
#pragma unroll
        for (int kk = 0; kk < 8; kk++) {
            const float4* ap = (const float4*)(&As[kk][ty * 8]);
            const float4* wp = (const float4*)(&Ws[kk][tx * 8]);
            float4 a0 = ap[0], a1 = ap[1];
            float4 w0 = wp[0], w1 = wp[1];
            float av[8] = {a0.x, a0.y, a0.z, a0.w, a1.x, a1.y, a1.z, a1.w};
            float wv[8] = {w0.x, w0.y, w0.z, w0.w, w1.x, w1.y, w1.z, w1.w};
#pragma unroll
            for (int i = 0; i < 8; i++)
#pragma unroll
                for (int j = 0; j < 8; j++) acc[i][j] += av[i] * wv[j];
        }
        __syncthreads();
    }
#pragma unroll
    for (int i = 0; i < 8; i++) {
        int m = bm + ty * 8 + i;
#pragma unroll
        for (int j = 0; j < 8; j++) {
            int n = bn + tx * 8 + j;
            C[(size_t)m * N + n] = acc[i][j] + b1[n] + b2[n];
        }
    }
}

__device__ __forceinline__ float sigf(float x) {
    return 1.f / (1.f + __expf(-x));
}

// ---------------- persistent bidirectional LSTM recurrence ------------------
// 128 CTAs: blockIdx/64 = direction. Each CTA owns 16 batches x 32 hidden
// units; Whh slice (128 rows x 256 k = 128KB) lives in smem for all 512 steps.
__global__ void __launch_bounds__(256, 1)
lstm_rec(const float* __restrict__ fWhh, const float* __restrict__ bWhh) {
    extern __shared__ float sm[];
    float* Wsm = sm;               // [256 k][4 gate][32 u]
    float* hsm = sm + 256 * 128;   // [16 b][256 k]

    int dir = blockIdx.x >> 6;
    int L = blockIdx.x & 63;
    int b0 = (L >> 3) * 16;
    int u0 = (L & 7) * 32;
    const float* Whh = dir ? bWhh : fWhh;
    const float* gx = dir ? g_gxb : g_gxf;
    int t = threadIdx.x;

    for (int i = t; i < 256 * 128; i += 256) {
        int k = i >> 7;
        int r = i & 127;
        int g = r >> 5;
        int u = r & 31;
        Wsm[i] = Whh[(size_t)(g * Hn + u0 + u) * Hn + k];
    }

    int u = t & 31, bp = t >> 5;
    int bl0 = bp * 2, bl1 = bl0 + 1;
    float c0 = 0.f, c1 = 0.f;
    volatile unsigned* cnt = &g_bar[dir];
    const float* wp = Wsm + u;

    for (int s = 0; s < Sn; s++) {
        int p = s & 1;
        const float* hprev = g_hbuf + (size_t)(p * 2 + dir) * Bn * Hn;
#pragma unroll
        for (int j = 0; j < 16; j++)
            hsm[j * Hn + t] = hprev[(b0 + j) * Hn + t];
        __syncthreads();

        int xs = dir ? ((Sn - s) & (Sn - 1)) : s;
        const float* gp0 = gx + ((size_t)xs * Bn + b0 + bl0) * G4 + u0 + u;
        const float* gp1 = gx + ((size_t)xs * Bn + b0 + bl1) * G4 + u0 + u;
        float a00 = gp0[0], a01 = gp0[256], a02 = gp0[512], a03 = gp0[768];
        float a10 = gp1[0], a11 = gp1[256], a12 = gp1[512], a13 = gp1[768];
        const float* h0p = hsm + bl0 * Hn;
        const float* h1p = hsm + bl1 * Hn;
#pragma unroll 8
        for (int k = 0; k < Hn; k++) {
            float w0 = wp[k * 128];
            float w1 = wp[k * 128 + 32];
            float w2 = wp[k * 128 + 64];
            float w3 = wp[k * 128 + 96];
            float x0 = h0p[k], x1 = h1p[k];
            a00 += x0 * w0; a01 += x0 * w1; a02 += x0 * w2; a03 += x0 * w3;
            a10 += x1 * w0; a11 += x1 * w1; a12 += x1 * w2; a13 += x1 * w3;
        }
        // gates i,f,g,o
        float i0 = sigf(a00), f0 = sigf(a01), gg0 = tanhf(a02), o0 = sigf(a03);
        c0 = f0 * c0 + i0 * gg0;
        float hv0 = o0 * tanhf(c0);
        float i1 = sigf(a10), f1 = sigf(a11), gg1 = tanhf(a12), o1 = sigf(a13);
        c1 = f1 * c1 + i1 * gg1;
        float hv1 = o1 * tanhf(c1);

        float* hnew = g_hbuf + (size_t)((1 - p) * 2 + dir) * Bn * Hn;
        hnew[(b0 + bl0) * Hn + u0 + u] = hv0;
        hnew[(b0 + bl1) * Hn + u0 + u] = hv1;

        __syncthreads();
        if (s < Sn - 1) {
            if (t == 0) {
                __threadfence();
                atomicAdd((unsigned*)&g_bar[dir], 1u);
                unsigned tgt = (unsigned)(s + 1) * GC;
                while (*cnt < tgt) {}
                __threadfence();
            }
            __syncthreads();
        }
    }
}

// ---------------- pack final fh|bh into decoder h0 --------------------------
__global__ void pack_h0() {
    int i = blockIdx.x * blockDim.x + threadIdx.x;
    if (i >= Bn * H2) return;
    int b = i >> 9, j = i & 511;
    // final h is in phase 0: [0][dir][b][k]
    g_hdec[0][i] = g_hbuf[(size_t)(j >> 8) * Bn * Hn + b * Hn + (j & 255)];
}

// ---------------- generic transpose: out[k][j] = in[j][k] -------------------
__global__ void transpose_kernel(const float* __restrict__ in,
                                 float* __restrict__ out, int J, int K) {
    int i = blockIdx.x * blockDim.x + threadIdx.x;
    if (i >= J * K) return;
    int j = i / K, k = i - j * K;
    out[k * J + j] = in[i];
}

// ---------------- decoder input gates: gxd[c] = tanh(ecW[cls]) @ dWih^T + bih
__global__ void gxd_kernel(const int* __restrict__ classes,
                           const float* __restrict__ ecW,
                           const float* __restrict__ dWih,
                           const float* __restrict__ dbih) {
    __shared__ float ce[En];
    int c = blockIdx.x;
    int cidx = classes[c];
    for (int e = threadIdx.x; e < En; e += blockDim.x)
        ce[e] = tanhf(ecW[(size_t)cidx * En + e]);
    __syncthreads();
    for (int j = threadIdx.x; j < G3; j += blockDim.x) {
        float acc = dbih[j];
        const float* w = dWih + (size_t)j * En;
        for (int e = 0; e < En; e++) acc += ce[e] * w[e];
        g_gxd[c * G3 + j] = acc;
    }
}

// ---------------- GRU decoder step: h_new = f(h, gxd[c]) --------------------
__global__ void dec_step1(int c, int srcp, const float* __restrict__ dbhh) {
    __shared__ float hsm[16 * H2];  // 32 KB
    const float* src = g_hdec[srcp];
    float* dst = g_hdec[1 - srcp];
    int b0 = blockIdx.y * 16;
    int u0 = blockIdx.x * 32;
    int t = threadIdx.x;
    for (int i = t; i < 16 * H2; i += 256)
        hsm[i] = src[(b0 + (i >> 9)) * H2 + (i & 511)];
    __syncthreads();

    int u = u0 + (t & 31);
    int bp = t >> 5;
    const float* h0p = hsm + (bp * 2) * H2;
    const float* h1p = hsm + (bp * 2 + 1) * H2;
    float r0 = 0, z0 = 0, n0 = 0, r1 = 0, z1 = 0, n1 = 0;
    const float* w = g_dT + u;
#pragma unroll 4
    for (int k = 0; k < H2; k++) {
        float wr = w[(size_t)k * G3];
        float wz = w[(size_t)k * G3 + 512];
        float wn = w[(size_t)k * G3 + 1024];
        float x0 = h0p[k], x1 = h1p[k];
        r0 += x0 * wr; z0 += x0 * wz; n0 += x0 * wn;
        r1 += x1 * wr; z1 += x1 * wz; n1 += x1 * wn;
    }
    float br = dbhh[u], bz = dbhh[512 + u], bn = dbhh[1024 + u];
    float gr = g_gxd[c * G3 + u];
    float gz = g_gxd[c * G3 + 512 + u];
    float gn = g_gxd[c * G3 + 1024 + u];

    float R0 = sigf(gr + r0 + br);
    float Z0 = sigf(gz + z0 + bz);
    float N0 = tanhf(gn + R0 * (n0 + bn));
    dst[(b0 + bp * 2) * H2 + u] = tanhf((1.f - Z0) * N0 + Z0 * h0p[u]);

    float R1 = sigf(gr + r1 + br);
    float Z1 = sigf(gz + z1 + bz);
    float N1 = tanhf(gn + R1 * (n1 + bn));
    dst[(b0 + bp * 2 + 1) * H2 + u] = tanhf((1.f - Z1) * N1 + Z1 * h1p[u]);
}

// ---------------- proj + cls + log_softmax, one CTA per batch row -----------
__global__ void dec_step2(int c, int hp, const float* __restrict__ projb,
                          const float* __restrict__ clsW,
                          const float* __restrict__ clsb,
                          float* __restrict__ out) {
    __shared__ float hsm[H2];
    __shared__ float r0s[256], r1s[256];
    int b = blockIdx.x;
    const float* h = g_hdec[hp] + (size_t)b * H2;
    int t = threadIdx.x;
    hsm[t] = h[t];
    hsm[t + 256] = h[t + 256];
    __syncthreads();
    float p = projb[t];
    const float* w = g_pT + t;
#pragma unroll 4
    for (int k = 0; k < H2; k++) p += hsm[k] * w[(size_t)k * Pn];
    r0s[t] = p * clsW[t];
    r1s[t] = p * clsW[256 + t];
    __syncthreads();
    for (int off = 128; off > 0; off >>= 1) {
        if (t < off) {
            r0s[t] += r0s[t + off];
            r1s[t] += r1s[t + off];
        }
        __syncthreads();
    }
    if (t == 0) {
        float l0 = r0s[0] + clsb[0], l1 = r1s[0] + clsb[1];
        float m = fmaxf(l0, l1);
        float lse = m + logf(expf(l0 - m) + expf(l1 - m));
        out[(c * Bn + b) * 2 + 0] = l0 - lse;
        out[(c * Bn + b) * 2 + 1] = l1 - lse;
    }
}

// ---------------- launch ----------------------------------------------------
extern "C" void kernel_launch(void* const* d_in, const int* in_sizes, int n_in,
                              void* d_out, int out_size) {
    const int*   seq     = (const int*)d_in[0];
    const int*   classes = (const int*)d_in[1];
    const float* embW    = (const float*)d_in[2];
    const float* ecW     = (const float*)d_in[3];
    const float* fWih    = (const float*)d_in[4];
    const float* fWhh    = (const float*)d_in[5];
    const float* fbih    = (const float*)d_in[6];
    const float* fbhh    = (const float*)d_in[7];
    const float* bWih    = (const float*)d_in[8];
    const float* bWhh    = (const float*)d_in[9];
    const float* bbih    = (const float*)d_in[10];
    const float* bbhh    = (const float*)d_in[11];
    const float* dWih    = (const float*)d_in[12];
    const float* dWhh    = (const float*)d_in[13];
    const float* dbih    = (const float*)d_in[14];
    const float* dbhh    = (const float*)d_in[15];
    const float* projW   = (const float*)d_in[16];
    const float* projb   = (const float*)d_in[17];
    const float* clsW    = (const float*)d_in[18];
    const float* clsb    = (const float*)d_in[19];
    float* out = (float*)d_out;

    const int lstm_smem = (256 * 128 + 16 * 256) * (int)sizeof(float);  // 147456
    cudaFuncSetAttribute(lstm_rec, cudaFuncAttributeMaxDynamicSharedMemorySize,
                         lstm_smem);

    float *emb_p, *gxf_p, *gxb_p, *dT_p, *pT_p;
    cudaGetSymbolAddress((void**)&emb_p, g_emb);
    cudaGetSymbolAddress((void**)&gxf_p, g_gxf);
    cudaGetSymbolAddress((void**)&gxb_p, g_gxb);
    cudaGetSymbolAddress((void**)&dT_p, g_dT);
    cudaGetSymbolAddress((void**)&pT_p, g_pT);

    reset_kernel<<<64, 256>>>();
    embed_kernel<<<Sn * Bn, 128>>>(seq, embW);

    dim3 ggrid(G4 / 128, (Sn * Bn) / 128);
    sgemm_nt<<<ggrid, 256>>>(emb_p, fWih, fbih, fbhh, gxf_p, Sn * Bn, G4, En);
    sgemm_nt<<<ggrid, 256>>>(emb_p, bWih, bbih, bbhh, gxb_p, Sn * Bn, G4, En);

    transpose_kernel<<<(G3 * H2 + 255) / 256, 256>>>(dWhh, dT_p, G3, H2);
    transpose_kernel<<<(Pn * H2 + 255) / 256, 256>>>(projW, pT_p, Pn, H2);
    gxd_kernel<<<Cn, 256>>>(classes, ecW, dWih, dbih);

    lstm_rec<<<2 * GC, 256, lstm_smem>>>(fWhh, bWhh);
    pack_h0<<<(Bn * H2 + 255) / 256, 256>>>();

    for (int c = 0; c < Cn; c++) {
        int sp = c & 1;
        dim3 dgrid(16, 8);
        dec_step1<<<dgrid, 256>>>(c, sp, dbhh);
        dec_step2<<<Bn, 256>>>(c, 1 - sp, projb, clsW, clsb, out);
    }
}

// round 8
// speedup vs baseline: 1.3595x; 1.3595x over previous
#include <cuda_runtime.h>
#include <math.h>

#define Sn 512
#define Bn 128
#define En 300
#define KP 304          // padded K for GEMM
#define Hn 256
#define Nc 2048         // combined gate width (fwd 1024 | bwd 1024)
#define Cn 6
#define Pn 256
#define H2 512
#define G3 1536
#define SAS 132         // padded smem tile stride in GEMM

typedef unsigned long long ull;

// ---------------- f32x2 helpers ---------------------------------------------
__device__ __forceinline__ ull fma2(ull a, ull b, ull c) {
    ull d; asm("fma.rn.f32x2 %0, %1, %2, %3;" : "=l"(d) : "l"(a), "l"(b), "l"(c));
    return d;
}
__device__ __forceinline__ ull add2(ull a, ull b) {
    ull d; asm("add.rn.f32x2 %0, %1, %2;" : "=l"(d) : "l"(a), "l"(b));
    return d;
}
__device__ __forceinline__ ull pack2(float x, float y) {
    ull d; asm("mov.b64 %0, {%1, %2};" : "=l"(d) : "f"(x), "f"(y));
    return d;
}
__device__ __forceinline__ float2 unpack2(ull p) {
    float2 r; asm("mov.b64 {%0, %1}, %2;" : "=f"(r.x), "=f"(r.y) : "l"(p));
    return r;
}
__device__ __forceinline__ float sigf(float x) { return 1.f / (1.f + __expf(-x)); }

// ---------------- scratch (static; no cudaMalloc) ---------------------------
__device__ float g_emb[Sn * Bn * KP];          // [S*B][304] zero-padded
__device__ float g_gx[(size_t)Sn * Bn * Nc];   // [S*B][2048] fwd|bwd gates
__device__ float g_Wc[Nc * KP];                // combined padded Wih
__device__ float g_bc[Nc];                     // combined bih+bhh
__device__ float g_hbuf[2 * 2 * Bn * Hn];      // [phase][dir][b][h]
__device__ float g_hdec[2][Bn * H2];
__device__ float g_gxd[Cn * G3];
__device__ float g_dT[H2 * G3];
__device__ float g_pT[H2 * Pn];
__device__ unsigned g_bar2[16];                // [dir][bgroup] barrier counters

// ---------------- reset -----------------------------------------------------
__global__ void reset_kernel() {
    int i = blockIdx.x * blockDim.x + threadIdx.x;
    if (i < 16) g_bar2[i] = 0u;
    for (int j = i; j < 2 * 2 * Bn * Hn; j += gridDim.x * blockDim.x)
        g_hbuf[j] = 0.f;
}

// ---------------- embedding: g_emb[s*128+b][0:300] = tanh(embed_W[tok]) -----
__global__ void embed_kernel(const int* __restrict__ seq,
                             const float* __restrict__ embW) {
    int m = blockIdx.x;              // m = s*128 + b
    int s = m >> 7, b = m & 127;
    int tok = seq[b * Sn + s];
    const float* src = embW + (size_t)tok * En;
    float* dst = g_emb + (size_t)m * KP;
    for (int e = threadIdx.x; e < En; e += blockDim.x)
        dst[e] = tanhf(src[e]);
}

// ---------------- build combined padded weights + bias ----------------------
__global__ void prep_w(const float* __restrict__ fWih, const float* __restrict__ bWih,
                       const float* __restrict__ fbih, const float* __restrict__ fbhh,
                       const float* __restrict__ bbih, const float* __restrict__ bbhh) {
    int i = blockIdx.x * blockDim.x + threadIdx.x;
    if (i < Nc * KP) {
        int n = i / KP, e = i - n * KP;
        float v = 0.f;
        if (e < En) v = (n < 1024) ? fWih[n * En + e] : bWih[(n - 1024) * En + e];
        g_Wc[i] = v;
    }
    if (i < Nc)
        g_bc[i] = (i < 1024) ? (fbih[i] + fbhh[i]) : (bbih[i - 1024] + bbhh[i - 1024]);
}

// ---------------- f32x2 SGEMM: C[M,2048] = A[M,304] * W[2048,304]^T + bias ---
// BM=BN=128, BK=16, 256 threads, 8x8 per thread on m-pairs, double-buffered.
__global__ void __launch_bounds__(256, 2)
sgemm2(const float* __restrict__ A, const float* __restrict__ W,
       const float* __restrict__ bias, float* __restrict__ C) {
    __shared__ float As[2][16 * SAS];
    __shared__ float Ws[2][16 * SAS];
    int bm = blockIdx.y * 128, bn = blockIdx.x * 128;
    int t = threadIdx.x;
    int tx = t & 15, ty = t >> 4;
    int row0 = t >> 2, c0 = t & 3;   // j0: rows 0..63
    int row1 = row0 + 64;            // j1: rows 64..127
    const float* Ap0 = A + (size_t)(bm + row0) * KP + c0 * 4;
    const float* Ap1 = A + (size_t)(bm + row1) * KP + c0 * 4;
    const float* Wp0 = W + (size_t)(bn + row0) * KP + c0 * 4;
    const float* Wp1 = W + (size_t)(bn + row1) * KP + c0 * 4;

    ull acc[4][8];
#pragma unroll
    for (int i = 0; i < 4; i++)
#pragma unroll
        for (int j = 0; j < 8; j++) acc[i][j] = 0ull;

    float4 ra0 = *(const float4*)(Ap0);
    float4 ra1 = *(const float4*)(Ap1);
    float4 rw0 = *(const float4*)(Wp0);
    float4 rw1 = *(const float4*)(Wp1);
    {
        float* as = As[0]; float* ws = Ws[0];
        int kb = c0 * 4;
        as[(kb + 0) * SAS + row0] = ra0.x; as[(kb + 1) * SAS + row0] = ra0.y;
        as[(kb + 2) * SAS + row0] = ra0.z; as[(kb + 3) * SAS + row0] = ra0.w;
        as[(kb + 0) * SAS + row1] = ra1.x; as[(kb + 1) * SAS + row1] = ra1.y;
        as[(kb + 2) * SAS + row1] = ra1.z; as[(kb + 3) * SAS + row1] = ra1.w;
        ws[(kb + 0) * SAS + row0] = rw0.x; ws[(kb + 1) * SAS + row0] = rw0.y;
        ws[(kb + 2) * SAS + row0] = rw0.z; ws[(kb + 3) * SAS + row0] = rw0.w;
        ws[(kb + 0) * SAS + row1] = rw1.x; ws[(kb + 1) * SAS + row1] = rw1.y;
        ws[(kb + 2) * SAS + row1] = rw1.z; ws[(kb + 3) * SAS + row1] = rw1.w;
    }
    __syncthreads();

#pragma unroll 1
    for (int it = 0; it < 19; it++) {
        int buf = it & 1;
        if (it < 18) {
            int k0 = (it + 1) * 16;
            ra0 = *(const float4*)(Ap0 + k0);
            ra1 = *(const float4*)(Ap1 + k0);
            rw0 = *(const float4*)(Wp0 + k0);
            rw1 = *(const float4*)(Wp1 + k0);
        }
        const float* as = As[buf];
        const float* ws = Ws[buf];
#pragma unroll 4
        for (int kk = 0; kk < 16; kk++) {
            const ull* ap = (const ull*)(as + kk * SAS + ty * 8);
            ull am[4] = {ap[0], ap[1], ap[2], ap[3]};
            const float4* bp = (const float4*)(ws + kk * SAS + tx * 8);
            float4 b0 = bp[0], b1 = bp[1];
            ull wv[8] = {pack2(b0.x, b0.x), pack2(b0.y, b0.y),
                         pack2(b0.z, b0.z), pack2(b0.w, b0.w),
                         pack2(b1.x, b1.x), pack2(b1.y, b1.y),
                         pack2(b1.z, b1.z), pack2(b1.w, b1.w)};
#pragma unroll
            for (int mp = 0; mp < 4; mp++)
#pragma unroll
                for (int n = 0; n < 8; n++)
                    acc[mp][n] = fma2(am[mp], wv[n], acc[mp][n]);
        }
        if (it < 18) {
            float* as2 = As[1 - buf]; float* ws2 = Ws[1 - buf];
            int kb = c0 * 4;
            as2[(kb + 0) * SAS + row0] = ra0.x; as2[(kb + 1) * SAS + row0] = ra0.y;
            as2[(kb + 2) * SAS + row0] = ra0.z; as2[(kb + 3) * SAS + row0] = ra0.w;
            as2[(kb + 0) * SAS + row1] = ra1.x; as2[(kb + 1) * SAS + row1] = ra1.y;
            as2[(kb + 2) * SAS + row1] = ra1.z; as2[(kb + 3) * SAS + row1] = ra1.w;
            ws2[(kb + 0) * SAS + row0] = rw0.x; ws2[(kb + 1) * SAS + row0] = rw0.y;
            ws2[(kb + 2) * SAS + row0] = rw0.z; ws2[(kb + 3) * SAS + row0] = rw0.w;
            ws2[(kb + 0) * SAS + row1] = rw1.x; ws2[(kb + 1) * SAS + row1] = rw1.y;
            ws2[(kb + 2) * SAS + row1] = rw1.z; ws2[(kb + 3) * SAS + row1] = rw1.w;
            __syncthreads();
        }
    }

    float4 bb0 = *(const float4*)(bias + bn + tx * 8);
    float4 bb1 = *(const float4*)(bias + bn + tx * 8 + 4);
#pragma unroll
    for (int mp = 0; mp < 4; mp++) {
        float2 h[8];
#pragma unroll
        for (int n = 0; n < 8; n++) h[n] = unpack2(acc[mp][n]);
        size_t m0 = (size_t)(bm + ty * 8 + mp * 2);
        float4 o;
        o.x = h[0].x + bb0.x; o.y = h[1].x + bb0.y; o.z = h[2].x + bb0.z; o.w = h[3].x + bb0.w;
        *(float4*)(C + m0 * Nc + bn + tx * 8) = o;
        o.x = h[4].x + bb1.x; o.y = h[5].x + bb1.y; o.z = h[6].x + bb1.z; o.w = h[7].x + bb1.w;
        *(float4*)(C + m0 * Nc + bn + tx * 8 + 4) = o;
        o.x = h[0].y + bb0.x; o.y = h[1].y + bb0.y; o.z = h[2].y + bb0.z; o.w = h[3].y + bb0.w;
        *(float4*)(C + (m0 + 1) * Nc + bn + tx * 8) = o;
        o.x = h[4].y + bb1.x; o.y = h[5].y + bb1.y; o.z = h[6].y + bb1.z; o.w = h[7].y + bb1.w;
        *(float4*)(C + (m0 + 1) * Nc + bn + tx * 8 + 4) = o;
    }
}

// ---------------- persistent bidirectional LSTM recurrence (v2) -------------
// 128 CTAs: dir = blk>>6. CTA tile: 16 batches (bg) x 32 units (u0).
// Warps partition K (warp w owns k in [w*32, w*32+32)); weights in smem read
// by exactly one warp; f32x2 packs batch pairs; cross-warp smem reduction;
// 8-CTA group barriers (only same-bg CTAs exchange h).
__global__ void __launch_bounds__(256, 1)
lstm2(const float* __restrict__ fWhh, const float* __restrict__ bWhh) {
    extern __shared__ float sm[];
    float* Wsm = sm;                       // [256 k][129 pad] (g*32+u in 0..127)
    ull* red = (ull*)(sm + 256 * 129);     // [8 w][4 g][8 bp][32 u]
    ull* hsm = red + 8192;                 // [256 k][9 pad] batch pairs

    int dir = blockIdx.x >> 6;
    int L = blockIdx.x & 63;
    int bg = L >> 3, u0 = (L & 7) * 32;
    int b0 = bg * 16;
    const float* Whh = dir ? bWhh : fWhh;
    const float* gx = g_gx + dir * 1024;
    int t = threadIdx.x, w = t >> 5, u = t & 31;

    // load Whh slice: Wsm[k*129 + g*32+uu] = Whh[(g*256+u0+uu)*256 + k]
    for (int i = t; i < 32768; i += 256) {
        int k = i & 255, r = i >> 8;
        int g = r >> 5, uu = r & 31;
        Wsm[k * 129 + r] = Whh[(size_t)(g * Hn + u0 + uu) * Hn + k];
    }
    float2 cc = make_float2(0.f, 0.f);
    volatile unsigned* cnt = &g_bar2[dir * 8 + bg];
    __syncthreads();

    for (int s = 0; s < Sn; s++) {
        int p = s & 1;
        // 1. transpose h_prev -> pair-packed hsm[k][bp]
        const float* hprev = g_hbuf + (size_t)(p * 2 + dir) * Bn * Hn;
#pragma unroll
        for (int j = 0; j < 16; j++) {
            float v = hprev[(b0 + j) * Hn + t];
            ((float*)(hsm + (t * 9 + (j >> 1))))[j & 1] = v;
        }
        __syncthreads();

        // prefetch gx for this thread's outputs (owner: bp=w, u)
        int xs = dir ? ((Sn - s) & (Sn - 1)) : s;
        const float* gp = gx + ((size_t)(xs * Bn + b0 + 2 * w)) * Nc + u0 + u;
        float ga0[4], ga1[4];
#pragma unroll
        for (int g = 0; g < 4; g++) {
            ga0[g] = gp[g * Hn];
            ga1[g] = gp[Nc + g * Hn];
        }

        // 2. partial gate dots over this warp's k slice
        ull acc[4][8];
#pragma unroll
        for (int g = 0; g < 4; g++)
#pragma unroll
            for (int bp = 0; bp < 8; bp++) acc[g][bp] = 0ull;
#pragma unroll 4
        for (int kk = 0; kk < 32; kk++) {
            int k = w * 32 + kk;
            const ull* hp = hsm + k * 9;
            ull hv[8] = {hp[0], hp[1], hp[2], hp[3], hp[4], hp[5], hp[6], hp[7]};
            const float* wr = Wsm + k * 129 + u;
            ull W0 = pack2(wr[0], wr[0]);
            ull W1 = pack2(wr[32], wr[32]);
            ull W2 = pack2(wr[64], wr[64]);
            ull W3 = pack2(wr[96], wr[96]);
#pragma unroll
            for (int bp = 0; bp < 8; bp++) {
                acc[0][bp] = fma2(W0, hv[bp], acc[0][bp]);
                acc[1][bp] = fma2(W1, hv[bp], acc[1][bp]);
                acc[2][bp] = fma2(W2, hv[bp], acc[2][bp]);
                acc[3][bp] = fma2(W3, hv[bp], acc[3][bp]);
            }
        }
        // 3. stash partials
#pragma unroll
        for (int g = 0; g < 4; g++)
#pragma unroll
            for (int bp = 0; bp < 8; bp++)
                red[((w * 4 + g) * 8 + bp) * 32 + u] = acc[g][bp];
        __syncthreads();

        // 4. reduce across warps; thread owns (bp=w, u)
        ull s0 = pack2(ga0[0], ga1[0]);
        ull s1 = pack2(ga0[1], ga1[1]);
        ull s2 = pack2(ga0[2], ga1[2]);
        ull s3 = pack2(ga0[3], ga1[3]);
#pragma unroll
        for (int ww = 0; ww < 8; ww++) {
            const ull* rp = red + ((ww * 4) * 8 + w) * 32 + u;
            s0 = add2(s0, rp[0]);
            s1 = add2(s1, rp[8 * 32]);
            s2 = add2(s2, rp[16 * 32]);
            s3 = add2(s3, rp[24 * 32]);
        }
        float2 iv = unpack2(s0), fv = unpack2(s1), gv = unpack2(s2), ov = unpack2(s3);
        cc.x = sigf(fv.x) * cc.x + sigf(iv.x) * tanhf(gv.x);
        cc.y = sigf(fv.y) * cc.y + sigf(iv.y) * tanhf(gv.y);
        float hx = sigf(ov.x) * tanhf(cc.x);
        float hy = sigf(ov.y) * tanhf(cc.y);

        // 5. publish h_new
        float* hnew = g_hbuf + (size_t)((1 - p) * 2 + dir) * Bn * Hn;
        hnew[(b0 + 2 * w) * Hn + u0 + u] = hx;
        hnew[(b0 + 2 * w + 1) * Hn + u0 + u] = hy;

        __syncthreads();
        // 6. 8-CTA group barrier (same dir, same bg)
        if (s < Sn - 1) {
            if (t == 0) {
                __threadfence();
                atomicAdd(&g_bar2[dir * 8 + bg], 1u);
                unsigned tgt = (unsigned)(s + 1) * 8u;
                while (*cnt < tgt) { __nanosleep(40); }
                __threadfence();
            }
            __syncthreads();
        }
    }
}

// ---------------- pack final fh|bh into decoder h0 --------------------------
__global__ void pack_h0() {
    int i = blockIdx.x * blockDim.x + threadIdx.x;
    if (i >= Bn * H2) return;
    int b = i >> 9, j = i & 511;
    g_hdec[0][i] = g_hbuf[(size_t)(j >> 8) * Bn * Hn + b * Hn + (j & 255)];
}

// ---------------- generic transpose -----------------------------------------
__global__ void transpose_kernel(const float* __restrict__ in,
                                 float* __restrict__ out, int J, int K) {
    int i = blockIdx.x * blockDim.x + threadIdx.x;
    if (i >= J * K) return;
    int j = i / K, k = i - j * K;
    out[k * J + j] = in[i];
}

// ---------------- decoder input gates ---------------------------------------
__global__ void gxd_kernel(const int* __restrict__ classes,
                           const float* __restrict__ ecW,
                           const float* __restrict__ dWih,
                           const float* __restrict__ dbih) {
    __shared__ float ce[En];
    int c = blockIdx.x;
    int cidx = classes[c];
    for (int e = threadIdx.x; e < En; e += blockDim.x)
        ce[e] = tanhf(ecW[(size_t)cidx * En + e]);
    __syncthreads();
    for (int j = threadIdx.x; j < G3; j += blockDim.x) {
        float acc = dbih[j];
        const float* w = dWih + (size_t)j * En;
        for (int e = 0; e < En; e++) acc += ce[e] * w[e];
        g_gxd[c * G3 + j] = acc;
    }
}

// ---------------- GRU decoder step ------------------------------------------
__global__ void dec_step1(int c, int srcp, const float* __restrict__ dbhh) {
    __shared__ float hsm[16 * H2];
    const float* src = g_hdec[srcp];
    float* dst = g_hdec[1 - srcp];
    int b0 = blockIdx.y * 16;
    int u0 = blockIdx.x * 32;
    int t = threadIdx.x;
    for (int i = t; i < 16 * H2; i += 256)
        hsm[i] = src[(b0 + (i >> 9)) * H2 + (i & 511)];
    __syncthreads();

    int u = u0 + (t & 31);
    int bp = t >> 5;
    const float* h0p = hsm + (bp * 2) * H2;
    const float* h1p = hsm + (bp * 2 + 1) * H2;
    float r0 = 0, z0 = 0, n0 = 0, r1 = 0, z1 = 0, n1 = 0;
    const float* w = g_dT + u;
#pragma unroll 4
    for (int k = 0; k < H2; k++) {
        float wr = w[(size_t)k * G3];
        float wz = w[(size_t)k * G3 + 512];
        float wn = w[(size_t)k * G3 + 1024];
        float x0 = h0p[k], x1 = h1p[k];
        r0 += x0 * wr; z0 += x0 * wz; n0 += x0 * wn;
        r1 += x1 * wr; z1 += x1 * wz; n1 += x1 * wn;
    }
    float br = dbhh[u], bz = dbhh[512 + u], bn = dbhh[1024 + u];
    float gr = g_gxd[c * G3 + u];
    float gz = g_gxd[c * G3 + 512 + u];
    float gn = g_gxd[c * G3 + 1024 + u];

    float R0 = sigf(gr + r0 + br);
    float Z0 = sigf(gz + z0 + bz);
    float N0 = tanhf(gn + R0 * (n0 + bn));
    dst[(b0 + bp * 2) * H2 + u] = tanhf((1.f - Z0) * N0 + Z0 * h0p[u]);

    float R1 = sigf(gr + r1 + br);
    float Z1 = sigf(gz + z1 + bz);
    float N1 = tanhf(gn + R1 * (n1 + bn));
    dst[(b0 + bp * 2 + 1) * H2 + u] = tanhf((1.f - Z1) * N1 + Z1 * h1p[u]);
}

// ---------------- proj + cls + log_softmax ----------------------------------
__global__ void dec_step2(int c, int hp, const float* __restrict__ projb,
                          const float* __restrict__ clsW,
                          const float* __restrict__ clsb,
                          float* __restrict__ out) {
    __shared__ float hsm[H2];
    __shared__ float r0s[256], r1s[256];
    int b = blockIdx.x;
    const float* h = g_hdec[hp] + (size_t)b * H2;
    int t = threadIdx.x;
    hsm[t] = h[t];
    hsm[t + 256] = h[t + 256];
    __syncthreads();
    float p = projb[t];
    const float* w = g_pT + t;
#pragma unroll 4
    for (int k = 0; k < H2; k++) p += hsm[k] * w[(size_t)k * Pn];
    r0s[t] = p * clsW[t];
    r1s[t] = p * clsW[256 + t];
    __syncthreads();
    for (int off = 128; off > 0; off >>= 1) {
        if (t < off) {
            r0s[t] += r0s[t + off];
            r1s[t] += r1s[t + off];
        }
        __syncthreads();
    }
    if (t == 0) {
        float l0 = r0s[0] + clsb[0], l1 = r1s[0] + clsb[1];
        float m = fmaxf(l0, l1);
        float lse = m + logf(expf(l0 - m) + expf(l1 - m));
        out[(c * Bn + b) * 2 + 0] = l0 - lse;
        out[(c * Bn + b) * 2 + 1] = l1 - lse;
    }
}

// ---------------- launch ----------------------------------------------------
extern "C" void kernel_launch(void* const* d_in, const int* in_sizes, int n_in,
                              void* d_out, int out_size) {
    const int*   seq     = (const int*)d_in[0];
    const int*   classes = (const int*)d_in[1];
    const float* embW    = (const float*)d_in[2];
    const float* ecW     = (const float*)d_in[3];
    const float* fWih    = (const float*)d_in[4];
    const float* fWhh    = (const float*)d_in[5];
    const float* fbih    = (const float*)d_in[6];
    const float* fbhh    = (const float*)d_in[7];
    const float* bWih    = (const float*)d_in[8];
    const float* bWhh    = (const float*)d_in[9];
    const float* bbih    = (const float*)d_in[10];
    const float* bbhh    = (const float*)d_in[11];
    const float* dWih    = (const float*)d_in[12];
    const float* dWhh    = (const float*)d_in[13];
    const float* dbih    = (const float*)d_in[14];
    const float* dbhh    = (const float*)d_in[15];
    const float* projW   = (const float*)d_in[16];
    const float* projb   = (const float*)d_in[17];
    const float* clsW    = (const float*)d_in[18];
    const float* clsb    = (const float*)d_in[19];
    float* out = (float*)d_out;

    const int lstm_smem = 256 * 129 * 4 + 8192 * 8 + 2304 * 8;  // 216064 B
    cudaFuncSetAttribute(lstm2, cudaFuncAttributeMaxDynamicSharedMemorySize,
                         lstm_smem);

    float *emb_p, *gx_p, *Wc_p, *bc_p, *dT_p, *pT_p;
    cudaGetSymbolAddress((void**)&emb_p, g_emb);
    cudaGetSymbolAddress((void**)&gx_p, g_gx);
    cudaGetSymbolAddress((void**)&Wc_p, g_Wc);
    cudaGetSymbolAddress((void**)&bc_p, g_bc);
    cudaGetSymbolAddress((void**)&dT_p, g_dT);
    cudaGetSymbolAddress((void**)&pT_p, g_pT);

    reset_kernel<<<64, 256>>>();
    embed_kernel<<<Sn * Bn, 128>>>(seq, embW);
    prep_w<<<(Nc * KP + 255) / 256, 256>>>(fWih, bWih, fbih, fbhh, bbih, bbhh);

    dim3 ggrid(Nc / 128, (Sn * Bn) / 128);
    sgemm2<<<ggrid, 256>>>(emb_p, Wc_p, bc_p, gx_p);

    transpose_kernel<<<(G3 * H2 + 255) / 256, 256>>>(dWhh, dT_p, G3, H2);
    transpose_kernel<<<(Pn * H2 + 255) / 256, 256>>>(projW, pT_p, Pn, H2);
    gxd_kernel<<<Cn, 256>>>(classes, ecW, dWih, dbih);

    lstm2<<<128, 256, lstm_smem>>>(fWhh, bWhh);
    pack_h0<<<(Bn * H2 + 255) / 256, 256>>>();

    for (int c = 0; c < Cn; c++) {
        int sp = c & 1;
        dim3 dgrid(16, 8);
        dec_step1<<<dgrid, 256>>>(c, sp, dbhh);
        dec_step2<<<Bn, 256>>>(c, 1 - sp, projb, clsW, clsb, out);
    }
}